// round 1
// baseline (speedup 1.0000x reference)
#include <cuda_runtime.h>

#define NODES   6272
#define CIN     8
#define COUT    16
#define CAPS    10
#define BATCH   64
#define CHUNK   64          // nodes per CTA in u_hat kernel
#define K1_THREADS 256
#define K2_THREADS 512
#define K2_WARPS   (K2_THREADS / 32)

// 257 MB scratch for u_hat[b][c][n][o], fully overwritten every launch.
__device__ float g_uhat[(size_t)BATCH * CAPS * NODES * COUT];

// ---------------------------------------------------------------------------
// Kernel 1: u_hat[b,c,n,o] = sum_i x[b,n,i] * W[c,n,i,o]
// Grid (NODES/CHUNK, CAPS). W chunk cached in SMEM then registers (reused
// across the whole batch loop); x chunk staged per-b in SMEM.
// Thread t owns node n = t/4 and output quad q = t%4 (4 consecutive o).
// ---------------------------------------------------------------------------
__global__ void __launch_bounds__(K1_THREADS)
uhat_kernel(const float* __restrict__ x, const float* __restrict__ W) {
    __shared__ float Ws[CHUNK * CIN * COUT];   // 32 KB
    __shared__ float xs[CHUNK * CIN];          // 2 KB

    const int c  = blockIdx.y;
    const int n0 = blockIdx.x * CHUNK;

    // Stage W chunk (8192 floats) into SMEM, coalesced float4.
    const float4* Wg = reinterpret_cast<const float4*>(
        W + ((size_t)c * NODES + n0) * (CIN * COUT));
    float4* Ws4 = reinterpret_cast<float4*>(Ws);
    #pragma unroll
    for (int i = threadIdx.x; i < CHUNK * CIN * COUT / 4; i += K1_THREADS)
        Ws4[i] = Wg[i];
    __syncthreads();

    const int t = threadIdx.x;
    const int n = t >> 2;    // node within chunk
    const int q = t & 3;     // output quad

    // Pull this thread's W column block into registers: W[n][i][4q .. 4q+3]
    float Wr[CIN][4];
    #pragma unroll
    for (int i = 0; i < CIN; i++)
        #pragma unroll
        for (int j = 0; j < 4; j++)
            Wr[i][j] = Ws[n * (CIN * COUT) + i * COUT + q * 4 + j];

    for (int b = 0; b < BATCH; b++) {
        __syncthreads();   // previous xs consumers done
        const float4* xg = reinterpret_cast<const float4*>(
            x + ((size_t)b * NODES + n0) * CIN);
        if (t < CHUNK * CIN / 4)
            reinterpret_cast<float4*>(xs)[t] = xg[t];
        __syncthreads();

        float xv[CIN];
        #pragma unroll
        for (int i = 0; i < CIN; i++) xv[i] = xs[n * CIN + i];

        float out[4] = {0.f, 0.f, 0.f, 0.f};
        #pragma unroll
        for (int i = 0; i < CIN; i++)
            #pragma unroll
            for (int j = 0; j < 4; j++)
                out[j] = fmaf(xv[i], Wr[i][j], out[j]);

        float4* og = reinterpret_cast<float4*>(
            g_uhat + (((size_t)b * CAPS + c) * NODES + (size_t)(n0 + n)) * COUT + q * 4);
        *og = make_float4(out[0], out[1], out[2], out[3]);
    }
}

// ---------------------------------------------------------------------------
// Kernel 2: dynamic routing, one CTA per (b, c). 3 streaming passes over the
// CTA's u_hat slice [NODES, 16]. Thread owns node rows (stride 512), keeps
// v[16] and acc[16] in registers; end-of-pass CTA reduction + squash.
// ---------------------------------------------------------------------------
__device__ __forceinline__ void cta_reduce_squash(
    float acc[COUT], float z, bool use_z, float inv_n,
    float* red, float* zred, float* v_sm, float* kf_sm,
    int tid, int lane, int warp, float vreg[COUT])
{
    // intra-warp reduce
    #pragma unroll
    for (int j = 0; j < COUT; j++) {
        float v = acc[j];
        #pragma unroll
        for (int ofs = 16; ofs > 0; ofs >>= 1)
            v += __shfl_xor_sync(0xffffffffu, v, ofs);
        acc[j] = v;
    }
    float zz = z;
    #pragma unroll
    for (int ofs = 16; ofs > 0; ofs >>= 1)
        zz += __shfl_xor_sync(0xffffffffu, zz, ofs);

    if (lane == 0) {
        #pragma unroll
        for (int j = 0; j < COUT; j++) red[warp * COUT + j] = acc[j];
        zred[warp] = zz;
    }
    __syncthreads();

    if (tid < COUT) {
        float s = 0.f, Z = 0.f;
        #pragma unroll
        for (int w = 0; w < K2_WARPS; w++) {
            s += red[w * COUT + tid];
            Z += zred[w];
        }
        float inv = use_z ? (1.f / Z) : inv_n;
        v_sm[tid] = s * inv;           // s_j component
    }
    __syncthreads();

    if (tid == 0) {
        float sq = 0.f;
        #pragma unroll
        for (int j = 0; j < COUT; j++) sq += v_sm[j] * v_sm[j];
        *kf_sm = sq / ((1.f + sq) * sqrtf(sq));   // squash factor
    }
    __syncthreads();

    const float kf = *kf_sm;
    #pragma unroll
    for (int j = 0; j < COUT; j++) vreg[j] = v_sm[j] * kf;
    __syncthreads();   // allow red/v_sm reuse next pass
}

__global__ void __launch_bounds__(K2_THREADS, 2)
routing_kernel(float* __restrict__ out) {
    __shared__ float a0_sm[NODES];            // cached iteration-1 logits
    __shared__ float red[K2_WARPS * COUT];
    __shared__ float zred[K2_WARPS];
    __shared__ float v_sm[COUT];
    __shared__ float kf_sm;

    const int c = blockIdx.x;
    const int b = blockIdx.y;
    const float* __restrict__ U =
        g_uhat + ((size_t)b * CAPS + c) * NODES * COUT;

    const int tid  = threadIdx.x;
    const int lane = tid & 31;
    const int warp = tid >> 5;

    float vreg[COUT];
    float acc[COUT];

    // ---- pass 0: s0 = mean_n u_hat  (softmax of zero logits is uniform) ----
    #pragma unroll
    for (int j = 0; j < COUT; j++) acc[j] = 0.f;
    for (int n = tid; n < NODES; n += K2_THREADS) {
        const float4* up = reinterpret_cast<const float4*>(U + (size_t)n * COUT);
        #pragma unroll
        for (int j4 = 0; j4 < 4; j4++) {
            float4 u = up[j4];
            acc[j4 * 4 + 0] += u.x;
            acc[j4 * 4 + 1] += u.y;
            acc[j4 * 4 + 2] += u.z;
            acc[j4 * 4 + 3] += u.w;
        }
    }
    cta_reduce_squash(acc, 0.f, false, 1.f / (float)NODES,
                      red, zred, v_sm, &kf_sm, tid, lane, warp, vreg);

    // ---- pass 1: a0 = u.v0 ; s1 = softmax_n(a0) . u ----
    #pragma unroll
    for (int j = 0; j < COUT; j++) acc[j] = 0.f;
    float z = 0.f;
    for (int n = tid; n < NODES; n += K2_THREADS) {
        const float4* up = reinterpret_cast<const float4*>(U + (size_t)n * COUT);
        float u[COUT];
        #pragma unroll
        for (int j4 = 0; j4 < 4; j4++) {
            float4 uu = up[j4];
            u[j4 * 4 + 0] = uu.x; u[j4 * 4 + 1] = uu.y;
            u[j4 * 4 + 2] = uu.z; u[j4 * 4 + 3] = uu.w;
        }
        float a = 0.f;
        #pragma unroll
        for (int j = 0; j < COUT; j++) a = fmaf(u[j], vreg[j], a);
        a0_sm[n] = a;
        float e = __expf(a);          // |a| bounded (~35) -> no max-sub needed
        z += e;
        #pragma unroll
        for (int j = 0; j < COUT; j++) acc[j] = fmaf(e, u[j], acc[j]);
    }
    cta_reduce_squash(acc, z, true, 0.f,
                      red, zred, v_sm, &kf_sm, tid, lane, warp, vreg);

    // ---- pass 2: b = a0 + u.v1 ; s2 = softmax_n(b) . u ; out = squash(s2) ----
    #pragma unroll
    for (int j = 0; j < COUT; j++) acc[j] = 0.f;
    z = 0.f;
    for (int n = tid; n < NODES; n += K2_THREADS) {
        const float4* up = reinterpret_cast<const float4*>(U + (size_t)n * COUT);
        float u[COUT];
        #pragma unroll
        for (int j4 = 0; j4 < 4; j4++) {
            float4 uu = up[j4];
            u[j4 * 4 + 0] = uu.x; u[j4 * 4 + 1] = uu.y;
            u[j4 * 4 + 2] = uu.z; u[j4 * 4 + 3] = uu.w;
        }
        float a = a0_sm[n];
        #pragma unroll
        for (int j = 0; j < COUT; j++) a = fmaf(u[j], vreg[j], a);
        float e = __expf(a);
        z += e;
        #pragma unroll
        for (int j = 0; j < COUT; j++) acc[j] = fmaf(e, u[j], acc[j]);
    }
    cta_reduce_squash(acc, z, true, 0.f,
                      red, zred, v_sm, &kf_sm, tid, lane, warp, vreg);

    if (tid < COUT)
        out[((size_t)b * CAPS + c) * COUT + tid] = vreg[tid];
}

// ---------------------------------------------------------------------------
extern "C" void kernel_launch(void* const* d_in, const int* in_sizes, int n_in,
                              void* d_out, int out_size) {
    const float* x = (const float*)d_in[0];
    const float* W = (const float*)d_in[1];
    // defensive: identify x by element count (x = 64*6272*8 = 3,211,264)
    if (in_sizes[0] != BATCH * NODES * CIN) {
        const float* tmp = x; x = W; W = tmp;
    }

    dim3 g1(NODES / CHUNK, CAPS);          // (98, 10)
    uhat_kernel<<<g1, K1_THREADS>>>(x, W);

    dim3 g2(CAPS, BATCH);                  // (10, 64)
    routing_kernel<<<g2, K2_THREADS>>>((float*)d_out);
}

// round 2
// speedup vs baseline: 1.6177x; 1.6177x over previous
#include <cuda_runtime.h>
#include <cuda_fp16.h>

#define NODES   6272
#define CIN     8
#define COUT    16
#define CAPS    10
#define BATCH   64
#define PAIRS   (BATCH * CAPS)          // 640
#define CHUNK   64                      // nodes per CTA in K1
#define NCHUNK  (NODES / CHUNK)         // 98
#define K1_THREADS 256
#define NSLICE  7                       // node slices per pair in pass kernels
#define SLICE   (NODES / NSLICE)        // 896
#define P_THREADS 224                   // 7 warps, 4 nodes/thread exactly
#define P_WARPS 7

// ---------------- device scratch (no allocation in kernel_launch) ----------
__device__ __half g_uh[(size_t)PAIRS * NODES * COUT];          // 128.4 MB fp16 u_hat
__device__ float  g_p0[(size_t)PAIRS * NCHUNK * COUT];         // K1 pass-0 partials (4 MB)
__device__ float  g_ps[(size_t)PAIRS * NSLICE * (COUT + 1)];   // pass partials (0.3 MB)
__device__ float  g_v0[PAIRS * COUT];                          // v after iter 0
__device__ float  g_vs[PAIRS * COUT];                          // v0 + v1

// ---------------- packed f32x2 helpers -------------------------------------
__device__ __forceinline__ unsigned long long pk2(float lo, float hi) {
    unsigned long long r;
    asm("mov.b64 %0, {%1, %2};" : "=l"(r) : "f"(lo), "f"(hi));
    return r;
}
__device__ __forceinline__ void upk2(unsigned long long v, float& lo, float& hi) {
    asm("mov.b64 {%0, %1}, %2;" : "=f"(lo), "=f"(hi) : "l"(v));
}
__device__ __forceinline__ unsigned long long fma2(unsigned long long a,
                                                   unsigned long long b,
                                                   unsigned long long c) {
    unsigned long long d;
    asm("fma.rn.f32x2 %0, %1, %2, %3;" : "=l"(d) : "l"(a), "l"(b), "l"(c));
    return d;
}

// ---------------------------------------------------------------------------
// K1: u_hat[b,c,n,:] = x[b,n,:] @ W[c,n,:,:], stored fp16.
// Also emits pass-0 partial sums (fp32, pre-quantization) per (b,c,chunk).
// Grid (NCHUNK, CAPS), 256 threads: thread = (node n = t/4, quad q = t&3).
// ---------------------------------------------------------------------------
__global__ void __launch_bounds__(K1_THREADS, 4)
uhat_kernel(const float* __restrict__ x, const float* __restrict__ W) {
    __shared__ float Ws[CHUNK * CIN * COUT];      // 32 KB
    __shared__ float xs[8 * CHUNK * CIN];         // 16 KB (8 batches staged)
    __shared__ float psum[2][8 * COUT];           // per-warp partials, dbl buf

    const int c  = blockIdx.y;
    const int n0 = blockIdx.x * CHUNK;
    const int t    = threadIdx.x;
    const int lane = t & 31;
    const int warp = t >> 5;
    const int n = t >> 2;
    const int q = t & 3;
    const size_t pair_base_c = (size_t)c;  // pair = b*CAPS + c

    // stage W chunk
    const float4* Wg = reinterpret_cast<const float4*>(
        W + ((size_t)c * NODES + n0) * (CIN * COUT));
    float4* Ws4 = reinterpret_cast<float4*>(Ws);
    #pragma unroll
    for (int i = t; i < CHUNK * CIN * COUT / 4; i += K1_THREADS)
        Ws4[i] = Wg[i];
    __syncthreads();

    // pack this thread's W block: W[n][i][4q..4q+3] as 2 f32x2 per i
    unsigned long long Wr2[CIN][2];
    #pragma unroll
    for (int i = 0; i < CIN; i++) {
        const float* wp = Ws + n * (CIN * COUT) + i * COUT + q * 4;
        Wr2[i][0] = pk2(wp[0], wp[1]);
        Wr2[i][1] = pk2(wp[2], wp[3]);
    }

    for (int bg = 0; bg < 8; bg++) {
        __syncthreads();
        // stage x for 8 batches: 1024 float4, 4 per thread
        #pragma unroll
        for (int k = 0; k < 4; k++) {
            int f  = t + k * K1_THREADS;
            int bi = f >> 7, r = f & 127;
            reinterpret_cast<float4*>(xs)[bi * 128 + r] =
                reinterpret_cast<const float4*>(
                    x + ((size_t)(bg * 8 + bi) * NODES + n0) * CIN)[r];
        }
        __syncthreads();

        #pragma unroll 2
        for (int bi = 0; bi < 8; bi++) {
            const int b = bg * 8 + bi;
            const float* xv = xs + bi * (CHUNK * CIN) + n * CIN;

            unsigned long long o20 = 0ull, o21 = 0ull;
            #pragma unroll
            for (int i = 0; i < CIN; i++) {
                unsigned long long x2 = pk2(xv[i], xv[i]);
                o20 = fma2(x2, Wr2[i][0], o20);
                o21 = fma2(x2, Wr2[i][1], o21);
            }
            float o0, o1, o2, o3;
            upk2(o20, o0, o1);
            upk2(o21, o2, o3);

            // fp16 store (8B, coalesced)
            __half2 h0 = __floats2half2_rn(o0, o1);
            __half2 h1 = __floats2half2_rn(o2, o3);
            uint2 st = make_uint2(*(unsigned*)&h0, *(unsigned*)&h1);
            *reinterpret_cast<uint2*>(
                g_uh + (((size_t)b * CAPS + c) * NODES + (n0 + n)) * COUT + q * 4) = st;

            // pass-0 partial: reduce over the warp's 8 nodes (lane bits 2..4)
            float r0 = o0, r1 = o1, r2 = o2, r3 = o3;
            #pragma unroll
            for (int ofs = 4; ofs <= 16; ofs <<= 1) {
                r0 += __shfl_xor_sync(0xffffffffu, r0, ofs);
                r1 += __shfl_xor_sync(0xffffffffu, r1, ofs);
                r2 += __shfl_xor_sync(0xffffffffu, r2, ofs);
                r3 += __shfl_xor_sync(0xffffffffu, r3, ofs);
            }
            const int buf = bi & 1;
            if (lane < 4) {
                float* p = psum[buf] + warp * COUT + lane * 4;
                p[0] = r0; p[1] = r1; p[2] = r2; p[3] = r3;
            }
            __syncthreads();
            if (t < COUT) {
                float s = 0.f;
                #pragma unroll
                for (int w = 0; w < 8; w++) s += psum[buf][w * COUT + t];
                g_p0[(((size_t)b * CAPS + c) * NCHUNK + blockIdx.x) * COUT + t] = s;
            }
        }
    }
    (void)pair_base_c;
}

// ---------------------------------------------------------------------------
// S0: v0 = squash(mean_n u_hat) from K1 partials. 640 blocks x 32 threads.
// ---------------------------------------------------------------------------
__global__ void squash0_kernel() {
    const int pair = blockIdx.x;
    const int lane = threadIdx.x;
    float s = 0.f;
    if (lane < COUT) {
        const float* p = g_p0 + (size_t)pair * NCHUNK * COUT + lane;
        #pragma unroll 7
        for (int ch = 0; ch < NCHUNK; ch++) s += p[ch * COUT];
        s *= (1.f / (float)NODES);
    }
    float sq = (lane < COUT) ? s * s : 0.f;
    #pragma unroll
    for (int ofs = 16; ofs > 0; ofs >>= 1)
        sq += __shfl_xor_sync(0xffffffffu, sq, ofs);
    float kf = sq / ((1.f + sq) * sqrtf(sq));
    if (lane < COUT) g_v0[pair * COUT + lane] = s * kf;
}

// ---------------------------------------------------------------------------
// Pass kernel: for tile (pair, slice): e_n = exp(u_n . v), emit partial
// (sum_n e_n * u_n, sum_n e_n). use_vs selects v = v0 (iter1) or v0+v1 (iter2).
// Grid (NSLICE, PAIRS), 224 threads, 4 nodes/thread.
// ---------------------------------------------------------------------------
__global__ void __launch_bounds__(P_THREADS, 5)
pass_kernel(int use_vs) {
    __shared__ float vsm[COUT];
    __shared__ float red[P_WARPS * (COUT + 1)];

    const int slice = blockIdx.x;
    const int pair  = blockIdx.y;
    const int tid   = threadIdx.x;
    const int lane  = tid & 31;
    const int warp  = tid >> 5;

    if (tid < COUT) {
        const float* vg = use_vs ? g_vs : g_v0;
        vsm[tid] = vg[pair * COUT + tid];
    }
    __syncthreads();

    const __half* __restrict__ U = g_uh + (size_t)pair * NODES * COUT;
    const int nbase = slice * SLICE;

    float acc[COUT];
    #pragma unroll
    for (int j = 0; j < COUT; j++) acc[j] = 0.f;
    float z = 0.f;

    #pragma unroll
    for (int k = 0; k < SLICE / P_THREADS; k++) {
        const int n = nbase + k * P_THREADS + tid;
        const uint4* p = reinterpret_cast<const uint4*>(U + (size_t)n * COUT);
        uint4 ra = p[0];
        uint4 rb = p[1];
        float u[COUT];
        {
            unsigned w[8] = {ra.x, ra.y, ra.z, ra.w, rb.x, rb.y, rb.z, rb.w};
            #pragma unroll
            for (int h = 0; h < 8; h++) {
                __half2 h2 = *reinterpret_cast<__half2*>(&w[h]);
                float2 f = __half22float2(h2);
                u[2 * h] = f.x; u[2 * h + 1] = f.y;
            }
        }
        float a = 0.f;
        #pragma unroll
        for (int j = 0; j < COUT; j++) a = fmaf(u[j], vsm[j], a);
        float e = __expf(a);
        z += e;
        #pragma unroll
        for (int j = 0; j < COUT; j++) acc[j] = fmaf(e, u[j], acc[j]);
    }

    // warp reduce 17 values
    #pragma unroll
    for (int j = 0; j < COUT; j++) {
        float v = acc[j];
        #pragma unroll
        for (int ofs = 16; ofs > 0; ofs >>= 1)
            v += __shfl_xor_sync(0xffffffffu, v, ofs);
        acc[j] = v;
    }
    #pragma unroll
    for (int ofs = 16; ofs > 0; ofs >>= 1)
        z += __shfl_xor_sync(0xffffffffu, z, ofs);

    if (lane == 0) {
        float* r = red + warp * (COUT + 1);
        #pragma unroll
        for (int j = 0; j < COUT; j++) r[j] = acc[j];
        r[COUT] = z;
    }
    __syncthreads();
    if (tid < COUT + 1) {
        float s = 0.f;
        #pragma unroll
        for (int w = 0; w < P_WARPS; w++) s += red[w * (COUT + 1) + tid];
        g_ps[((size_t)pair * NSLICE + slice) * (COUT + 1) + tid] = s;
    }
}

// ---------------------------------------------------------------------------
// S12: reduce pass partials, softmax-normalize, squash.
// stage==1: g_vs = v0 + squash(s/z).  stage==2: out = squash(s/z).
// ---------------------------------------------------------------------------
__global__ void squash12_kernel(int stage, float* __restrict__ out) {
    const int pair = blockIdx.x;
    const int lane = threadIdx.x;
    float s = 0.f;
    if (lane < COUT + 1) {
        const float* p = g_ps + (size_t)pair * NSLICE * (COUT + 1) + lane;
        #pragma unroll
        for (int sl = 0; sl < NSLICE; sl++) s += p[sl * (COUT + 1)];
    }
    float z = __shfl_sync(0xffffffffu, s, COUT);
    float sj = (lane < COUT) ? s * (1.f / z) : 0.f;
    float sq = sj * sj;
    #pragma unroll
    for (int ofs = 16; ofs > 0; ofs >>= 1)
        sq += __shfl_xor_sync(0xffffffffu, sq, ofs);
    float kf = sq / ((1.f + sq) * sqrtf(sq));
    float v = sj * kf;
    if (lane < COUT) {
        if (stage == 1)
            g_vs[pair * COUT + lane] = g_v0[pair * COUT + lane] + v;
        else
            out[pair * COUT + lane] = v;
    }
}

// ---------------------------------------------------------------------------
extern "C" void kernel_launch(void* const* d_in, const int* in_sizes, int n_in,
                              void* d_out, int out_size) {
    const float* x = (const float*)d_in[0];
    const float* W = (const float*)d_in[1];
    if (in_sizes[0] != BATCH * NODES * CIN) {
        const float* tmp = x; x = W; W = tmp;
    }

    uhat_kernel<<<dim3(NCHUNK, CAPS), K1_THREADS>>>(x, W);
    squash0_kernel<<<PAIRS, 32>>>();
    pass_kernel<<<dim3(NSLICE, PAIRS), P_THREADS>>>(0);
    squash12_kernel<<<PAIRS, 32>>>(1, nullptr);
    pass_kernel<<<dim3(NSLICE, PAIRS), P_THREADS>>>(1);
    squash12_kernel<<<PAIRS, 32>>>(2, (float*)d_out);
}